// round 8
// baseline (speedup 1.0000x reference)
#include <cuda_runtime.h>
#include <cuda_bf16.h>
#include <stdint.h>
#include <math.h>

#define BSZ   32
#define NPAT  576
#define WCON  32
#define DDIM  256
#define MROWS (BSZ*NPAT)   // 18432 patches
#define NCON  (BSZ*WCON)   // 1024 concepts

#define CT 128             // concepts per CTA tile (M)
#define PT 256             // patches per tile (N)
#define NT_N (MROWS/PT)    // 72 patch tiles
#define NT_C (NCON/CT)     // 8 concept tiles
#define PPG  4             // patch tiles per CTA
#define NPG  (NT_N/PPG)    // 18 -> grid 18 x 8 = 144 CTAs (1 wave)
#define NCHUNK (4*PPG)     // 16 B-chunks per CTA

// scratch (device globals; no allocation allowed)
__device__ __nv_bfloat16 g_conb[NCON * DDIM];
__device__ __nv_bfloat16 g_imgb[MROWS * DDIM];
__device__ unsigned      g_enc[NCON * BSZ];     // running max[concept j][image m], encoded

// ---------------- helpers ----------------
static __device__ __forceinline__ uint32_t smem_u32(const void* p) {
    uint32_t a;
    asm("{ .reg .u64 t; cvta.to.shared.u64 t, %1; cvt.u32.u64 %0, t; }" : "=r"(a) : "l"(p));
    return a;
}
static __device__ __forceinline__ unsigned enc_f(float f) {
    unsigned b = __float_as_uint(f);
    return (b & 0x80000000u) ? ~b : (b | 0x80000000u);
}
static __device__ __forceinline__ float dec_f(unsigned u) {
    unsigned b = (u & 0x80000000u) ? (u & 0x7FFFFFFFu) : ~u;
    return __uint_as_float(b);
}
static __device__ __forceinline__ void cpasync16(uint32_t dst, const void* src) {
    asm volatile("cp.async.cg.shared.global [%0], [%1], 16;" :: "r"(dst), "l"(src));
}
static __device__ __forceinline__ void ldsm_x4(uint32_t* r, uint32_t addr) {
    asm volatile("ldmatrix.sync.aligned.m8n8.x4.shared.b16 {%0,%1,%2,%3}, [%4];"
                 : "=r"(r[0]), "=r"(r[1]), "=r"(r[2]), "=r"(r[3]) : "r"(addr));
}
static __device__ __forceinline__ void mma_bf16(float* c, const uint32_t* a, const uint32_t* b) {
    asm volatile("mma.sync.aligned.m16n8k16.row.col.f32.bf16.bf16.f32 "
                 "{%0,%1,%2,%3}, {%4,%5,%6,%7}, {%8,%9}, {%0,%1,%2,%3};"
                 : "+f"(c[0]), "+f"(c[1]), "+f"(c[2]), "+f"(c[3])
                 : "r"(a[0]), "r"(a[1]), "r"(a[2]), "r"(a[3]), "r"(b[0]), "r"(b[1]));
}

// ---------------------------------------------------------------------------
// Fused: L2-normalize img+con rows (fp32 -> bf16) + g_enc zero-init.
// ---------------------------------------------------------------------------
__global__ void __launch_bounds__(256) prep_kernel(const float* __restrict__ img,
                                                   const float* __restrict__ con) {
    if (blockIdx.x < 16) {
        int idx = blockIdx.x * 2048 + threadIdx.x * 8;
#pragma unroll
        for (int k = 0; k < 8; k++) g_enc[idx + k] = 0u;
    }

    int gw = blockIdx.x * 8 + (threadIdx.x >> 5);
    int lane = threadIdx.x & 31;
    const float* in;
    __nv_bfloat16* out;
    int row;
    if (gw < MROWS)             { in = img; out = g_imgb; row = gw; }
    else if (gw < MROWS + NCON) { in = con; out = g_conb; row = gw - MROWS; }
    else return;

    const float4* ip = reinterpret_cast<const float4*>(in + (size_t)row * DDIM);
    float4 v0 = ip[lane];
    float4 v1 = ip[lane + 32];
    float s = v0.x*v0.x + v0.y*v0.y + v0.z*v0.z + v0.w*v0.w
            + v1.x*v1.x + v1.y*v1.y + v1.z*v1.z + v1.w*v1.w;
#pragma unroll
    for (int o = 16; o > 0; o >>= 1) s += __shfl_xor_sync(0xffffffffu, s, o);
    float r = 1.0f / fmaxf(sqrtf(s), 1e-12f);

    __nv_bfloat162* op = reinterpret_cast<__nv_bfloat162*>(out + (size_t)row * DDIM);
    op[lane * 2 + 0]      = __floats2bfloat162_rn(v0.x * r, v0.y * r);
    op[lane * 2 + 1]      = __floats2bfloat162_rn(v0.z * r, v0.w * r);
    op[64 + lane * 2 + 0] = __floats2bfloat162_rn(v1.x * r, v1.y * r);
    op[64 + lane * 2 + 1] = __floats2bfloat162_rn(v1.z * r, v1.w * r);
}

// ---------------------------------------------------------------------------
// Single-wave fused GEMM + max-over-patches, LDSM-traffic-minimized.
// Grid (NPG, NT_C) = 144 CTAs, 256 threads = 8 warps (2m x 4n), warp tile 64x64.
// A (128 x K=256) resident: 64KB. B: 4-stage ring of 32KB chunks: 128KB.
// One __syncthreads per chunk; stage t+3 issued after the sync that retires
// compute of t-1 (whose buffer it reuses).
// ---------------------------------------------------------------------------
#define SMA_CHUNK (CT * 128)           // 16KB per A k-chunk
#define SMA_BYTES (4 * SMA_CHUNK)      // 64KB
#define SMB_CHUNK (PT * 128)           // 32KB per B chunk buffer
#define SMEM_DYN  (SMA_BYTES + 4 * SMB_CHUNK)   // 192KB

static __device__ __forceinline__ void stage_B(int ptile, int kc, uint32_t buf, int tid) {
    const __nv_bfloat16* bsrc = g_imgb + (size_t)ptile * PT * DDIM + kc * 64;
#pragma unroll
    for (int i = tid; i < 2048; i += 256) {
        int r = i >> 3, s = i & 7;
        cpasync16(buf + r * 128 + ((s ^ (r & 7)) << 4), bsrc + (size_t)r * DDIM + s * 8);
    }
}

static __device__ __forceinline__ void compute_chunk(float acc[4][8][4],
                                                     uint32_t bufA, uint32_t bufB,
                                                     int warp_m, int warp_n, int lane) {
#pragma unroll
    for (int ks = 0; ks < 4; ks++) {
        uint32_t a[4][4];
#pragma unroll
        for (int mi = 0; mi < 4; mi++) {
            int row = warp_m * 64 + mi * 16 + (lane & 15);
            uint32_t g = ((ks << 1) + (lane >> 4)) ^ (row & 7);
            ldsm_x4(a[mi], bufA + row * 128 + (g << 4));
        }
        uint32_t b[4][4];
#pragma unroll
        for (int pi = 0; pi < 4; pi++) {
            int nloc = warp_n * 64 + pi * 16 + ((lane >> 4) << 3) + (lane & 7);
            uint32_t g = ((ks << 1) + ((lane >> 3) & 1)) ^ (nloc & 7);
            ldsm_x4(b[pi], bufB + nloc * 128 + (g << 4));
        }
#pragma unroll
        for (int mi = 0; mi < 4; mi++)
#pragma unroll
            for (int pi = 0; pi < 4; pi++) {
                mma_bf16(acc[mi][2 * pi + 0], a[mi], &b[pi][0]);
                mma_bf16(acc[mi][2 * pi + 1], a[mi], &b[pi][2]);
            }
    }
}

__global__ void __launch_bounds__(256, 1) sim_mma_kernel() {
    extern __shared__ char sm[];
    const int pgrp  = blockIdx.x;
    const int ctile = blockIdx.y;
    const int tid = threadIdx.x;
    const int wid = tid >> 5;
    const int lane = tid & 31;
    const int warp_m = wid & 1;        // 2 warps in m (64 rows each)
    const int warp_n = wid >> 1;       // 4 warps in n (64 cols each)
    const int pt0 = pgrp * PPG;

    uint32_t A = smem_u32(sm);
    uint32_t B[4];
#pragma unroll
    for (int i = 0; i < 4; i++) B[i] = A + SMA_BYTES + i * SMB_CHUNK;

    // Stage resident A tile (all 4 k-chunks) + prime B chunks 0..2.
    {
        const __nv_bfloat16* asrc = g_conb + (size_t)ctile * CT * DDIM;
#pragma unroll
        for (int i = tid; i < 4096; i += 256) {
            int r = i >> 5, u = i & 31;
            int kc = u >> 3, s = u & 7;
            cpasync16(A + kc * SMA_CHUNK + r * 128 + ((s ^ (r & 7)) << 4),
                      asrc + (size_t)r * DDIM + kc * 64 + s * 8);
        }
    }
    stage_B(pt0, 0, B[0], tid);
    asm volatile("cp.async.commit_group;" ::: "memory");   // g0: A + B0
    stage_B(pt0, 1, B[1], tid);
    asm volatile("cp.async.commit_group;" ::: "memory");   // g1
    stage_B(pt0, 2, B[2], tid);
    asm volatile("cp.async.commit_group;" ::: "memory");   // g2

    float acc[4][8][4];
    for (int t = 0; t < NCHUNK; t++) {
        int kc = t & 3;
        if (kc == 0) {
#pragma unroll
            for (int mi = 0; mi < 4; mi++)
#pragma unroll
                for (int ni = 0; ni < 8; ni++)
#pragma unroll
                    for (int c = 0; c < 4; c++) acc[mi][ni][c] = 0.f;
        }

        asm volatile("cp.async.wait_group 2;" ::: "memory");   // chunk t resident
        __syncthreads();                                       // also retires compute t-1

        int tn = t + 3;
        if (tn < NCHUNK) stage_B(pt0 + (tn >> 2), tn & 3, B[tn & 3], tid);
        asm volatile("cp.async.commit_group;" ::: "memory");

        compute_chunk(acc, A + kc * SMA_CHUNK, B[t & 3], warp_m, warp_n, lane);

        if (kc == 3) {
            // Epilogue for finished ptile (overlaps in-flight staging).
            const int ptile = pt0 + (t >> 2);
            const int p0 = ptile * PT;
            const int m0 = p0 / NPAT;
            const int b  = (m0 + 1) * NPAT - p0;   // image boundary (even, in (0,576])
#pragma unroll
            for (int mi = 0; mi < 4; mi++) {
                float mx00 = -1e30f, mx01 = -1e30f;
                float mx10 = -1e30f, mx11 = -1e30f;
#pragma unroll
                for (int ni = 0; ni < 8; ni++) {
                    int lc = warp_n * 64 + ni * 8 + (lane & 3) * 2;
                    if (lc < b) {
                        mx00 = fmaxf(mx00, fmaxf(acc[mi][ni][0], acc[mi][ni][1]));
                        mx10 = fmaxf(mx10, fmaxf(acc[mi][ni][2], acc[mi][ni][3]));
                    } else {
                        mx01 = fmaxf(mx01, fmaxf(acc[mi][ni][0], acc[mi][ni][1]));
                        mx11 = fmaxf(mx11, fmaxf(acc[mi][ni][2], acc[mi][ni][3]));
                    }
                }
#pragma unroll
                for (int o = 1; o <= 2; o <<= 1) {
                    mx00 = fmaxf(mx00, __shfl_xor_sync(0xffffffffu, mx00, o));
                    mx01 = fmaxf(mx01, __shfl_xor_sync(0xffffffffu, mx01, o));
                    mx10 = fmaxf(mx10, __shfl_xor_sync(0xffffffffu, mx10, o));
                    mx11 = fmaxf(mx11, __shfl_xor_sync(0xffffffffu, mx11, o));
                }
                if ((lane & 3) == 0) {
                    int r0 = ctile * CT + warp_m * 64 + mi * 16 + (lane >> 2);
                    atomicMax(&g_enc[r0 * BSZ + m0],       enc_f(mx00));
                    atomicMax(&g_enc[(r0 + 8) * BSZ + m0], enc_f(mx10));
                    if (b < PT) {
                        atomicMax(&g_enc[r0 * BSZ + m0 + 1],       enc_f(mx01));
                        atomicMax(&g_enc[(r0 + 8) * BSZ + m0 + 1], enc_f(mx11));
                    }
                }
            }
        }
    }
}

// ---------------------------------------------------------------------------
// Final: masked mean over ragged concepts + log-sigmoid + mean reduce.
// ---------------------------------------------------------------------------
__global__ void __launch_bounds__(1024) loss_kernel(const int* __restrict__ lens,
                                                    const float* __restrict__ scale_p,
                                                    const float* __restrict__ bias_p,
                                                    float* __restrict__ out) {
    int tid = threadIdx.x;
    int m = tid >> 5, c = tid & 31;
    int L = lens[c];
    float s = 0.f;
#pragma unroll
    for (int w = 0; w < WCON; w++) {
        if (w < L) s += dec_f(g_enc[((c << 5) + w) * BSZ + m]);
    }
    float sim = s / (float)L;
    float t = expf(fminf(fmaxf(scale_p[0], -10.f), 10.f));
    float logit = fminf(fmaxf(t * sim + bias_p[0], -50.f), 50.f);
    float z = (m == c) ? 1.f : -1.f;
    float zx = z * logit;
    float term = -(fminf(zx, 0.f) - log1pf(expf(-fabsf(zx))));

#pragma unroll
    for (int o = 16; o > 0; o >>= 1) term += __shfl_xor_sync(0xffffffffu, term, o);
    __shared__ float red[32];
    if ((tid & 31) == 0) red[tid >> 5] = term;
    __syncthreads();
    if (tid < 32) {
        float v = red[tid];
#pragma unroll
        for (int o = 16; o > 0; o >>= 1) v += __shfl_xor_sync(0xffffffffu, v, o);
        if (tid == 0) out[0] = v * (1.0f / (BSZ * BSZ));
    }
}

extern "C" void kernel_launch(void* const* d_in, const int* in_sizes, int n_in,
                              void* d_out, int out_size) {
    const float* img = nullptr; const float* con = nullptr;
    const int* lens = nullptr; const float* sc = nullptr; const float* bi = nullptr;
    for (int i = 0; i < n_in; i++) {
        int s = in_sizes[i];
        if (s == MROWS * DDIM)      img = (const float*)d_in[i];
        else if (s == NCON * DDIM)  con = (const float*)d_in[i];
        else if (s == BSZ)          lens = (const int*)d_in[i];
        else if (s == 1) { if (!sc) sc = (const float*)d_in[i]; else bi = (const float*)d_in[i]; }
    }

    cudaFuncSetAttribute(sim_mma_kernel, cudaFuncAttributeMaxDynamicSharedMemorySize, SMEM_DYN);

    prep_kernel<<<(MROWS + NCON + 7) / 8, 256>>>(img, con);

    dim3 grid(NPG, NT_C);
    sim_mma_kernel<<<grid, 256, SMEM_DYN>>>();

    loss_kernel<<<1, 1024>>>(lens, sc, bi, (float*)d_out);
}